// round 6
// baseline (speedup 1.0000x reference)
#include <cuda_runtime.h>
#include <cuda_bf16.h>
#include <cstdint>

// Problem constants
#define N_ROWS 131072
#define DDIM   1024
#define KCENT  256
#define M_TILE 128
#define N_HALF 128                   // centroid columns per CTA (cluster of 2)
#define KCHUNK 64                    // bf16 elems per D-chunk (128 B rows)
#define NCHUNKS (DDIM / KCHUNK)      // 16

#define A_BYTES (M_TILE * 128)       // 16384
#define B_BYTES (N_HALF * 128)       // 16384
#define STAGE   (A_BYTES + B_BYTES)  // 32768
#define SM_NORM (2 * STAGE)          // float[128]
#define SM_PART (SM_NORM + 512)      // float[4*128]
#define SM_MINE (SM_PART + 2048)     // float[128] partial exp-sums (DSMEM peer-read)
#define SM_INV  (SM_MINE + 512)      // float[128]
#define SMEM_TOTAL (SM_INV + 512)

// Normalized centroids, bf16, [K][D] (512 KB device scratch, L2-resident)
__device__ __align__(16) __nv_bfloat16 g_cn[KCENT * DDIM];

// ---------------------------------------------------------------------------
// PTX helpers
// ---------------------------------------------------------------------------
__device__ __forceinline__ unsigned smem_u32(const void* p) {
    return (unsigned)__cvta_generic_to_shared(p);
}
__device__ __forceinline__ void ldmatrix_x4(unsigned r[4], unsigned addr) {
    asm volatile("ldmatrix.sync.aligned.m8n8.x4.shared.b16 {%0,%1,%2,%3}, [%4];"
                 : "=r"(r[0]), "=r"(r[1]), "=r"(r[2]), "=r"(r[3]) : "r"(addr));
}
__device__ __forceinline__ void mma_16816(float d[4], const unsigned a[4],
                                          unsigned b0, unsigned b1) {
    asm volatile(
        "mma.sync.aligned.m16n8k16.row.col.f32.bf16.bf16.f32 "
        "{%0,%1,%2,%3}, {%4,%5,%6,%7}, {%8,%9}, {%0,%1,%2,%3};"
        : "+f"(d[0]), "+f"(d[1]), "+f"(d[2]), "+f"(d[3])
        : "r"(a[0]), "r"(a[1]), "r"(a[2]), "r"(a[3]), "r"(b0), "r"(b1));
}
__device__ __forceinline__ void cp_async16(unsigned saddr, const void* gaddr) {
    asm volatile("cp.async.cg.shared.global [%0], [%1], 16;"
                 :: "r"(saddr), "l"(gaddr) : "memory");
}
__device__ __forceinline__ void cp_commit() {
    asm volatile("cp.async.commit_group;" ::: "memory");
}
__device__ __forceinline__ void cp_wait0() {
    asm volatile("cp.async.wait_group 0;" ::: "memory");
}
__device__ __forceinline__ void sts128(unsigned addr, uint4 v) {
    asm volatile("st.shared.v4.b32 [%0], {%1, %2, %3, %4};"
                 :: "r"(addr), "r"(v.x), "r"(v.y), "r"(v.z), "r"(v.w) : "memory");
}
__device__ __forceinline__ unsigned cluster_rank() {
    unsigned r;
    asm("mov.u32 %0, %%cluster_ctarank;" : "=r"(r));
    return r;
}
__device__ __forceinline__ void cluster_sync() {
    asm volatile("barrier.cluster.arrive.aligned;" ::: "memory");
    asm volatile("barrier.cluster.wait.aligned;" ::: "memory");
}

// ---------------------------------------------------------------------------
// Prepass: normalize centroids (fp32) -> bf16 scratch. 256 blocks x 256 thr.
// ---------------------------------------------------------------------------
__global__ void centroid_prep_kernel(const float* __restrict__ cent) {
    int b = blockIdx.x;
    int t = threadIdx.x;
    const float4 v = reinterpret_cast<const float4*>(cent + (size_t)b * DDIM)[t];
    float s = v.x * v.x + v.y * v.y + v.z * v.z + v.w * v.w;
    #pragma unroll
    for (int o = 16; o; o >>= 1) s += __shfl_xor_sync(0xFFFFFFFFu, s, o);
    __shared__ float ws[8];
    __shared__ float s_inv;
    if ((t & 31) == 0) ws[t >> 5] = s;
    __syncthreads();
    if (t == 0) {
        float tot = 0.f;
        #pragma unroll
        for (int i = 0; i < 8; i++) tot += ws[i];
        s_inv = 1.0f / fmaxf(sqrtf(tot), 1e-8f);
    }
    __syncthreads();
    float iv = s_inv;
    __nv_bfloat16* dst = g_cn + (size_t)b * DDIM + t * 4;
    dst[0] = __float2bfloat16(v.x * iv);
    dst[1] = __float2bfloat16(v.y * iv);
    dst[2] = __float2bfloat16(v.z * iv);
    dst[3] = __float2bfloat16(v.w * iv);
}

// ---------------------------------------------------------------------------
// Main kernel: cluster of 2 CTAs; each CTA 256 thr computes 128x128 half,
// 8 warps (2x4), warp tile 64x32, SW128 swizzle, double-buffered stages.
// Row softmax sums exchanged across the cluster via DSMEM.
// ---------------------------------------------------------------------------
__global__ void __launch_bounds__(256, 2) __cluster_dims__(2, 1, 1)
cluster_hmma_kernel(const float* __restrict__ batch, float* __restrict__ out) {
    extern __shared__ char smem[];
    const unsigned sb = smem_u32(smem);
    const int tid  = threadIdx.x;
    const int lane = tid & 31;
    const int w    = tid >> 5;
    const int m0   = (blockIdx.x >> 1) * M_TILE;
    const unsigned rank = cluster_rank();
    const int c0   = (int)rank * N_HALF;

    const int rowGroup = (w & 1) * 64;    // 0 or 64
    const int colGroup = (w >> 1) * 32;   // 0,32,64,96 within this CTA's half

    // A producer: 2 threads per row, 32 floats each
    const int arow  = tid >> 1;
    const int ahalf = tid & 1;
    const unsigned axor = (unsigned)((arow & 7) << 4);
    const float* aptr = batch + (size_t)(m0 + arow) * DDIM + ahalf * 32;
    // B producer: rows (t>>3)+i*32 of this half, 16B granule (t&7)
    const int brow0 = tid >> 3;
    const int bcol  = tid & 7;
    const unsigned bxor = (unsigned)((brow0 & 7) << 4);

    float psq = 0.f;
    float acc[4][4][4];
    #pragma unroll
    for (int mt = 0; mt < 4; mt++)
        #pragma unroll
        for (int nt = 0; nt < 4; nt++)
            #pragma unroll
            for (int c = 0; c < 4; c++) acc[mt][nt][c] = 0.f;

    auto loadA = [&](int ch, float4 v[8]) {
        const float4* p = reinterpret_cast<const float4*>(aptr + ch * KCHUNK);
        #pragma unroll
        for (int i = 0; i < 8; i++) v[i] = p[i];
    };
    auto storeA = [&](unsigned base, float4 v[8]) {
        #pragma unroll
        for (int i = 0; i < 8; i++)
            psq += v[i].x * v[i].x + v[i].y * v[i].y +
                   v[i].z * v[i].z + v[i].w * v[i].w;
        #pragma unroll
        for (int j = 0; j < 4; j++) {
            __nv_bfloat162 p0 = __floats2bfloat162_rn(v[2*j].x,   v[2*j].y);
            __nv_bfloat162 p1 = __floats2bfloat162_rn(v[2*j].z,   v[2*j].w);
            __nv_bfloat162 p2 = __floats2bfloat162_rn(v[2*j+1].x, v[2*j+1].y);
            __nv_bfloat162 p3 = __floats2bfloat162_rn(v[2*j+1].z, v[2*j+1].w);
            uint4 pk;
            pk.x = *reinterpret_cast<unsigned*>(&p0);
            pk.y = *reinterpret_cast<unsigned*>(&p1);
            pk.z = *reinterpret_cast<unsigned*>(&p2);
            pk.w = *reinterpret_cast<unsigned*>(&p3);
            unsigned col = (unsigned)(ahalf * 64 + j * 16) ^ axor;
            sts128(base + (unsigned)(arow * 128) + col, pk);
        }
    };
    auto loadB = [&](int ch, unsigned base) {
        const unsigned col = ((unsigned)(bcol * 16)) ^ bxor;
        #pragma unroll
        for (int i = 0; i < 4; i++) {
            int r = brow0 + i * 32;
            cp_async16(base + (unsigned)(r * 128) + col,
                       g_cn + (size_t)(c0 + r) * DDIM + ch * KCHUNK + bcol * 8);
        }
    };

    // ldmatrix per-lane bases (row&7 is lane-constant in both patterns)
    const unsigned sxor = (unsigned)((lane & 7) << 4);
    const unsigned aFragBase = (unsigned)((rowGroup + (lane & 15)) * 128);
    const unsigned aKsel = (unsigned)((lane >> 4) * 16);
    const unsigned bFragBase =
        (unsigned)((colGroup + (lane & 7) + ((lane >> 4) << 3)) * 128);
    const unsigned bKsel = (unsigned)(((lane >> 3) & 1) * 16);

    // ---- prologue: stage 0 ----
    {
        float4 v[8];
        loadA(0, v);
        loadB(0, sb + A_BYTES);
        cp_commit();
        storeA(sb, v);
        cp_wait0();
    }
    __syncthreads();

    float4 av[8];

    #pragma unroll 1
    for (int ch = 0; ch < NCHUNKS; ch++) {
        const unsigned cur = sb + (unsigned)((ch & 1) * STAGE);
        const unsigned nxt = sb + (unsigned)(((ch + 1) & 1) * STAGE);

        if (ch < NCHUNKS - 1) {
            loadA(ch + 1, av);               // LDG in flight during compute
            loadB(ch + 1, nxt + A_BYTES);
            cp_commit();
        }

        const unsigned aB = cur + aFragBase;
        const unsigned bB = cur + A_BYTES + bFragBase;

        #pragma unroll
        for (int kk = 0; kk < 4; kk++) {
            const unsigned aCol = ((unsigned)(kk * 32) + aKsel) ^ sxor;
            const unsigned bCol = ((unsigned)(kk * 32) + bKsel) ^ sxor;
            unsigned af[4][4];
            #pragma unroll
            for (int mt = 0; mt < 4; mt++)
                ldmatrix_x4(af[mt], aB + (unsigned)(mt * 16 * 128) + aCol);
            unsigned bf[2][4];
            #pragma unroll
            for (int nt2 = 0; nt2 < 2; nt2++)
                ldmatrix_x4(bf[nt2], bB + (unsigned)(nt2 * 16 * 128) + bCol);
            #pragma unroll
            for (int nt2 = 0; nt2 < 2; nt2++)
                #pragma unroll
                for (int mt = 0; mt < 4; mt++) {
                    mma_16816(acc[mt][2*nt2],     af[mt], bf[nt2][0], bf[nt2][1]);
                    mma_16816(acc[mt][2*nt2 + 1], af[mt], bf[nt2][2], bf[nt2][3]);
                }
        }

        if (ch < NCHUNKS - 1) {
            storeA(nxt, av);
            cp_wait0();
        }
        __syncthreads();
    }

    // ---- row norms (2 producer threads per row) ----
    {
        float tot = psq + __shfl_xor_sync(0xFFFFFFFFu, psq, 1);
        if (!ahalf)
            reinterpret_cast<float*>(smem + SM_NORM)[arow] =
                1.0f / fmaxf(sqrtf(tot), 1e-8f);
    }
    __syncthreads();

    const float* smN = reinterpret_cast<const float*>(smem + SM_NORM);
    float* smP = reinterpret_cast<float*>(smem + SM_PART);
    float* smM = reinterpret_cast<float*>(smem + SM_MINE);
    float* smI = reinterpret_cast<float*>(smem + SM_INV);

    // ---- exp in place + row partial sums over this CTA's 128 cols ----
    float rsum[4][2];
    #pragma unroll
    for (int mt = 0; mt < 4; mt++) {
        const int r0 = rowGroup + mt * 16 + (lane >> 2);
        const float in0 = smN[r0], in1 = smN[r0 + 8];
        float s0 = 0.f, s1 = 0.f;
        #pragma unroll
        for (int nt = 0; nt < 4; nt++) {
            float e0 = __expf(acc[mt][nt][0] * in0);
            float e1 = __expf(acc[mt][nt][1] * in0);
            float e2 = __expf(acc[mt][nt][2] * in1);
            float e3 = __expf(acc[mt][nt][3] * in1);
            acc[mt][nt][0] = e0; acc[mt][nt][1] = e1;
            acc[mt][nt][2] = e2; acc[mt][nt][3] = e3;
            s0 += e0 + e1;
            s1 += e2 + e3;
        }
        rsum[mt][0] = s0;
        rsum[mt][1] = s1;
    }
    #pragma unroll
    for (int mt = 0; mt < 4; mt++)
        #pragma unroll
        for (int rh = 0; rh < 2; rh++) {
            float s = rsum[mt][rh];
            s += __shfl_xor_sync(0xFFFFFFFFu, s, 1);
            s += __shfl_xor_sync(0xFFFFFFFFu, s, 2);
            rsum[mt][rh] = s;
        }
    if ((lane & 3) == 0) {
        const int cg = (w >> 1) * 128;   // 4 column groups
        #pragma unroll
        for (int mt = 0; mt < 4; mt++)
            #pragma unroll
            for (int rh = 0; rh < 2; rh++)
                smP[cg + rowGroup + mt * 16 + (lane >> 2) + 8 * rh] = rsum[mt][rh];
    }
    __syncthreads();
    if (tid < 128)
        smM[tid] = smP[tid] + smP[128 + tid] + smP[256 + tid] + smP[384 + tid];

    // ---- cluster exchange of partial sums via DSMEM ----
    cluster_sync();                       // peer's smM visible
    if (tid < 128) {
        unsigned laddr = sb + SM_MINE + (unsigned)(tid * 4);
        unsigned raddr;
        asm("mapa.shared::cluster.u32 %0, %1, %2;"
            : "=r"(raddr) : "r"(laddr), "r"(rank ^ 1u));
        float pv;
        asm volatile("ld.shared::cluster.f32 %0, [%1];" : "=f"(pv) : "r"(raddr));
        smI[tid] = 1.0f / (smM[tid] + pv);
    }
    cluster_sync();                       // remote reads done before either exits
    __syncthreads();

    // ---- scaled stores ----
    #pragma unroll
    for (int mt = 0; mt < 4; mt++) {
        const int r0 = rowGroup + mt * 16 + (lane >> 2);
        const float is0 = smI[r0], is1 = smI[r0 + 8];
        float* o0 = out + (size_t)(m0 + r0) * KCENT + c0 + colGroup + (lane & 3) * 2;
        float* o1 = o0 + (size_t)8 * KCENT;
        #pragma unroll
        for (int nt = 0; nt < 4; nt++) {
            float2 v0 = make_float2(acc[mt][nt][0] * is0, acc[mt][nt][1] * is0);
            float2 v1 = make_float2(acc[mt][nt][2] * is1, acc[mt][nt][3] * is1);
            *reinterpret_cast<float2*>(o0 + nt * 8) = v0;
            *reinterpret_cast<float2*>(o1 + nt * 8) = v1;
        }
    }
}

// ---------------------------------------------------------------------------
extern "C" void kernel_launch(void* const* d_in, const int* in_sizes, int n_in,
                              void* d_out, int out_size) {
    const float* batch     = (const float*)d_in[0];   // [N, D] fp32
    const float* centroids = (const float*)d_in[1];   // [K, D] fp32
    float* out = (float*)d_out;                       // [N, K] fp32

    centroid_prep_kernel<<<KCENT, 256>>>(centroids);

    cudaFuncSetAttribute(cluster_hmma_kernel,
                         cudaFuncAttributeMaxDynamicSharedMemorySize, SMEM_TOTAL);
    cluster_hmma_kernel<<<(N_ROWS / M_TILE) * 2, 256, SMEM_TOTAL>>>(batch, out);
}

// round 8
// speedup vs baseline: 1.8121x; 1.8121x over previous
#include <cuda_runtime.h>
#include <cuda_bf16.h>
#include <cstdint>

// Problem constants
#define N_ROWS 131072
#define DDIM   1024
#define KCENT  256
#define M_TILE 64                    // rows per CTA
#define KCHUNK 64                    // bf16 elems per D-chunk (128 B rows)
#define NCHUNKS (DDIM / KCHUNK)      // 16

#define A_BYTES (M_TILE * 128)       // 8192
#define B_BYTES (KCENT * 128)        // 32768
#define STAGE   (A_BYTES + B_BYTES)  // 40960
#define SM_NORM (2 * STAGE)          // float[64]
#define SM_PART (SM_NORM + 256)      // float[8*64]
#define SM_INV  (SM_PART + 2048)     // float[64]
#define SMEM_TOTAL (SM_INV + 256)

// Normalized centroids, bf16, [K][D] (512 KB device scratch, L2-resident)
__device__ __align__(16) __nv_bfloat16 g_cn[KCENT * DDIM];

// ---------------------------------------------------------------------------
// PTX helpers
// ---------------------------------------------------------------------------
__device__ __forceinline__ unsigned smem_u32(const void* p) {
    return (unsigned)__cvta_generic_to_shared(p);
}
__device__ __forceinline__ void ldmatrix_x4(unsigned r[4], unsigned addr) {
    asm volatile("ldmatrix.sync.aligned.m8n8.x4.shared.b16 {%0,%1,%2,%3}, [%4];"
                 : "=r"(r[0]), "=r"(r[1]), "=r"(r[2]), "=r"(r[3]) : "r"(addr));
}
__device__ __forceinline__ void mma_16816(float d[4], const unsigned a[4],
                                          unsigned b0, unsigned b1) {
    asm volatile(
        "mma.sync.aligned.m16n8k16.row.col.f32.bf16.bf16.f32 "
        "{%0,%1,%2,%3}, {%4,%5,%6,%7}, {%8,%9}, {%0,%1,%2,%3};"
        : "+f"(d[0]), "+f"(d[1]), "+f"(d[2]), "+f"(d[3])
        : "r"(a[0]), "r"(a[1]), "r"(a[2]), "r"(a[3]), "r"(b0), "r"(b1));
}
__device__ __forceinline__ void cp_async16(unsigned saddr, const void* gaddr) {
    asm volatile("cp.async.cg.shared.global [%0], [%1], 16;"
                 :: "r"(saddr), "l"(gaddr) : "memory");
}
__device__ __forceinline__ void cp_commit() {
    asm volatile("cp.async.commit_group;" ::: "memory");
}
__device__ __forceinline__ void cp_wait0() {
    asm volatile("cp.async.wait_group 0;" ::: "memory");
}
__device__ __forceinline__ void sts128(unsigned addr, uint4 v) {
    asm volatile("st.shared.v4.b32 [%0], {%1, %2, %3, %4};"
                 :: "r"(addr), "r"(v.x), "r"(v.y), "r"(v.z), "r"(v.w) : "memory");
}

// ---------------------------------------------------------------------------
// Prepass: normalize centroids (fp32) -> bf16 scratch. 256 blocks x 256 thr.
// ---------------------------------------------------------------------------
__global__ void centroid_prep_kernel(const float* __restrict__ cent) {
    int b = blockIdx.x;
    int t = threadIdx.x;
    const float4 v = reinterpret_cast<const float4*>(cent + (size_t)b * DDIM)[t];
    float s = v.x * v.x + v.y * v.y + v.z * v.z + v.w * v.w;
    #pragma unroll
    for (int o = 16; o; o >>= 1) s += __shfl_xor_sync(0xFFFFFFFFu, s, o);
    __shared__ float ws[8];
    __shared__ float s_inv;
    if ((t & 31) == 0) ws[t >> 5] = s;
    __syncthreads();
    if (t == 0) {
        float tot = 0.f;
        #pragma unroll
        for (int i = 0; i < 8; i++) tot += ws[i];
        s_inv = 1.0f / fmaxf(sqrtf(tot), 1e-8f);
    }
    __syncthreads();
    float iv = s_inv;
    __nv_bfloat16* dst = g_cn + (size_t)b * DDIM + t * 4;
    dst[0] = __float2bfloat16(v.x * iv);
    dst[1] = __float2bfloat16(v.y * iv);
    dst[2] = __float2bfloat16(v.z * iv);
    dst[3] = __float2bfloat16(v.w * iv);
}

// ---------------------------------------------------------------------------
// Main kernel: 64x256 CTA tile, 8 warps (1x8), warp tile 64x32, SW128
// swizzle, double-buffered stages, 2 independent CTAs/SM, fused softmax.
// ---------------------------------------------------------------------------
__global__ void __launch_bounds__(256, 2)
cluster_hmma_kernel(const float* __restrict__ batch, float* __restrict__ out) {
    extern __shared__ char smem[];
    const unsigned sb = smem_u32(smem);
    const int tid  = threadIdx.x;
    const int lane = tid & 31;
    const int w    = tid >> 5;
    const int m0   = blockIdx.x * M_TILE;

    const int colGroup = w * 32;          // warp's 32 centroid columns

    // A producer: 4 threads per row, 16 floats each
    const int arow = tid >> 2;
    const int aq   = tid & 3;
    const unsigned axor = (unsigned)((arow & 7) << 4);
    const float* aptr = batch + (size_t)(m0 + arow) * DDIM + aq * 16;
    // B producer: rows (t>>3)+i*32, 16B granule (t&7)
    const int brow0 = tid >> 3;
    const int bcol  = tid & 7;
    const unsigned bxor = (unsigned)((brow0 & 7) << 4);

    float psq = 0.f;
    float acc[4][4][4];
    #pragma unroll
    for (int mt = 0; mt < 4; mt++)
        #pragma unroll
        for (int nt = 0; nt < 4; nt++)
            #pragma unroll
            for (int c = 0; c < 4; c++) acc[mt][nt][c] = 0.f;

    auto loadA = [&](int ch, float4 v[4]) {
        const float4* p = reinterpret_cast<const float4*>(aptr + ch * KCHUNK);
        #pragma unroll
        for (int i = 0; i < 4; i++) v[i] = p[i];
    };
    auto storeA = [&](unsigned base, float4 v[4]) {
        #pragma unroll
        for (int i = 0; i < 4; i++)
            psq += v[i].x * v[i].x + v[i].y * v[i].y +
                   v[i].z * v[i].z + v[i].w * v[i].w;
        #pragma unroll
        for (int j = 0; j < 2; j++) {
            __nv_bfloat162 p0 = __floats2bfloat162_rn(v[2*j].x,   v[2*j].y);
            __nv_bfloat162 p1 = __floats2bfloat162_rn(v[2*j].z,   v[2*j].w);
            __nv_bfloat162 p2 = __floats2bfloat162_rn(v[2*j+1].x, v[2*j+1].y);
            __nv_bfloat162 p3 = __floats2bfloat162_rn(v[2*j+1].z, v[2*j+1].w);
            uint4 pk;
            pk.x = *reinterpret_cast<unsigned*>(&p0);
            pk.y = *reinterpret_cast<unsigned*>(&p1);
            pk.z = *reinterpret_cast<unsigned*>(&p2);
            pk.w = *reinterpret_cast<unsigned*>(&p3);
            unsigned col = (unsigned)(aq * 32 + j * 16) ^ axor;
            sts128(base + (unsigned)(arow * 128) + col, pk);
        }
    };
    auto loadB = [&](int ch, unsigned base) {
        const unsigned col = ((unsigned)(bcol * 16)) ^ bxor;
        #pragma unroll
        for (int i = 0; i < 8; i++) {
            int r = brow0 + i * 32;
            cp_async16(base + (unsigned)(r * 128) + col,
                       g_cn + (size_t)r * DDIM + ch * KCHUNK + bcol * 8);
        }
    };

    // ldmatrix per-lane bases (row&7 is lane-constant in both patterns)
    const unsigned sxor = (unsigned)((lane & 7) << 4);
    const unsigned aFragBase = (unsigned)((lane & 15) * 128);
    const unsigned aKsel = (unsigned)((lane >> 4) * 16);
    const unsigned bFragBase =
        (unsigned)((colGroup + (lane & 7) + ((lane >> 4) << 3)) * 128);
    const unsigned bKsel = (unsigned)(((lane >> 3) & 1) * 16);

    // ---- prologue: stage 0 ----
    {
        float4 v[4];
        loadA(0, v);
        loadB(0, sb + A_BYTES);
        cp_commit();
        storeA(sb, v);
        cp_wait0();
    }
    __syncthreads();

    float4 av[4];

    #pragma unroll 1
    for (int ch = 0; ch < NCHUNKS; ch++) {
        const unsigned cur = sb + (unsigned)((ch & 1) * STAGE);
        const unsigned nxt = sb + (unsigned)(((ch + 1) & 1) * STAGE);

        if (ch < NCHUNKS - 1) {
            loadA(ch + 1, av);               // LDG in flight during compute
            loadB(ch + 1, nxt + A_BYTES);
            cp_commit();
        }

        const unsigned aB = cur + aFragBase;
        const unsigned bB = cur + A_BYTES + bFragBase;

        #pragma unroll
        for (int kk = 0; kk < 4; kk++) {
            const unsigned aCol = ((unsigned)(kk * 32) + aKsel) ^ sxor;
            const unsigned bCol = ((unsigned)(kk * 32) + bKsel) ^ sxor;
            unsigned af[4][4];
            #pragma unroll
            for (int mt = 0; mt < 4; mt++)
                ldmatrix_x4(af[mt], aB + (unsigned)(mt * 16 * 128) + aCol);
            unsigned bf[2][4];
            #pragma unroll
            for (int nt2 = 0; nt2 < 2; nt2++)
                ldmatrix_x4(bf[nt2], bB + (unsigned)(nt2 * 16 * 128) + bCol);
            #pragma unroll
            for (int nt2 = 0; nt2 < 2; nt2++)
                #pragma unroll
                for (int mt = 0; mt < 4; mt++) {
                    mma_16816(acc[mt][2*nt2],     af[mt], bf[nt2][0], bf[nt2][1]);
                    mma_16816(acc[mt][2*nt2 + 1], af[mt], bf[nt2][2], bf[nt2][3]);
                }
        }

        if (ch < NCHUNKS - 1) {
            storeA(nxt, av);
            cp_wait0();
        }
        __syncthreads();
    }

    // ---- row norms (4 producer threads per row) ----
    {
        float tot = psq;
        tot += __shfl_xor_sync(0xFFFFFFFFu, tot, 1);
        tot += __shfl_xor_sync(0xFFFFFFFFu, tot, 2);
        if (aq == 0)
            reinterpret_cast<float*>(smem + SM_NORM)[arow] =
                1.0f / fmaxf(sqrtf(tot), 1e-8f);
    }
    __syncthreads();

    const float* smN = reinterpret_cast<const float*>(smem + SM_NORM);
    float* smP = reinterpret_cast<float*>(smem + SM_PART);
    float* smI = reinterpret_cast<float*>(smem + SM_INV);

    // ---- exp in place + row partial sums ----
    float rsum[4][2];
    #pragma unroll
    for (int mt = 0; mt < 4; mt++) {
        const int r0 = mt * 16 + (lane >> 2);
        const float in0 = smN[r0], in1 = smN[r0 + 8];
        float s0 = 0.f, s1 = 0.f;
        #pragma unroll
        for (int nt = 0; nt < 4; nt++) {
            float e0 = __expf(acc[mt][nt][0] * in0);
            float e1 = __expf(acc[mt][nt][1] * in0);
            float e2 = __expf(acc[mt][nt][2] * in1);
            float e3 = __expf(acc[mt][nt][3] * in1);
            acc[mt][nt][0] = e0; acc[mt][nt][1] = e1;
            acc[mt][nt][2] = e2; acc[mt][nt][3] = e3;
            s0 += e0 + e1;
            s1 += e2 + e3;
        }
        rsum[mt][0] = s0;
        rsum[mt][1] = s1;
    }
    #pragma unroll
    for (int mt = 0; mt < 4; mt++)
        #pragma unroll
        for (int rh = 0; rh < 2; rh++) {
            float s = rsum[mt][rh];
            s += __shfl_xor_sync(0xFFFFFFFFu, s, 1);
            s += __shfl_xor_sync(0xFFFFFFFFu, s, 2);
            rsum[mt][rh] = s;
        }
    if ((lane & 3) == 0) {
        #pragma unroll
        for (int mt = 0; mt < 4; mt++)
            #pragma unroll
            for (int rh = 0; rh < 2; rh++)
                smP[w * 64 + mt * 16 + (lane >> 2) + 8 * rh] = rsum[mt][rh];
    }
    __syncthreads();
    if (tid < 64) {
        float s = 0.f;
        #pragma unroll
        for (int g = 0; g < 8; g++) s += smP[g * 64 + tid];
        smI[tid] = 1.0f / s;
    }
    __syncthreads();

    // ---- scaled stores ----
    #pragma unroll
    for (int mt = 0; mt < 4; mt++) {
        const int r0 = mt * 16 + (lane >> 2);
        const float is0 = smI[r0], is1 = smI[r0 + 8];
        float* o0 = out + (size_t)(m0 + r0) * KCENT + colGroup + (lane & 3) * 2;
        float* o1 = o0 + (size_t)8 * KCENT;
        #pragma unroll
        for (int nt = 0; nt < 4; nt++) {
            float2 v0 = make_float2(acc[mt][nt][0] * is0, acc[mt][nt][1] * is0);
            float2 v1 = make_float2(acc[mt][nt][2] * is1, acc[mt][nt][3] * is1);
            *reinterpret_cast<float2*>(o0 + nt * 8) = v0;
            *reinterpret_cast<float2*>(o1 + nt * 8) = v1;
        }
    }
}

// ---------------------------------------------------------------------------
extern "C" void kernel_launch(void* const* d_in, const int* in_sizes, int n_in,
                              void* d_out, int out_size) {
    const float* batch     = (const float*)d_in[0];   // [N, D] fp32
    const float* centroids = (const float*)d_in[1];   // [K, D] fp32
    float* out = (float*)d_out;                       // [N, K] fp32

    centroid_prep_kernel<<<KCENT, 256>>>(centroids);

    cudaFuncSetAttribute(cluster_hmma_kernel,
                         cudaFuncAttributeMaxDynamicSharedMemorySize, SMEM_TOTAL);
    cluster_hmma_kernel<<<N_ROWS / M_TILE, 256, SMEM_TOTAL>>>(batch, out);
}